// round 8
// baseline (speedup 1.0000x reference)
#include <cuda_runtime.h>

// ---------------- static scratch (no dynamic allocation allowed) ------------
#define MAXN 50016
#define MAXE 800000

__device__ float g_H1[MAXN * 64];   // layer-1 features x@W1
__device__ float g_as1[MAXN * 4];   // alpha_src layer1 per head (x@v1)
__device__ float g_ad1[MAXN * 4];   // alpha_dst layer1 per head
__device__ float g_X2[MAXN * 64];   // elu(gat1 output) = input to layer2
__device__ float g_H2[MAXN * 32];   // layer-2 features X2@W2
__device__ float g_as2[MAXN];
__device__ float g_ad2[MAXN];
__device__ int   g_deg[MAXN];       // zero at load; re-zeroed each run in scan
__device__ int   g_rowptr[MAXN + 1];
__device__ int   g_wpos[MAXN + 1];
__device__ int   g_csrsrc[MAXE];
__device__ float4 g_w1[MAXE];       // layer-1 edge weights (4 heads), CSR order
__device__ int   g_bsums[64];
__device__ float g_v1[8 * 128];     // [out][k]: 0-3 = W1@a_src1 heads, 4-7 = W1@a_dst1
__device__ float g_v2s[64];         // W2@a_src2
__device__ float g_v2d[64];         // W2@a_dst2

// ---------------- L1: pre (block 0) ⊕ histogram ------------------------------
__global__ void k_pre_hist(const float* __restrict__ W1,
                           const float* __restrict__ a_src1, const float* __restrict__ a_dst1,
                           const float* __restrict__ W2,
                           const float* __restrict__ a_src2, const float* __restrict__ a_dst2,
                           const int* __restrict__ ei, int E) {
    int t = threadIdx.x;
    if (blockIdx.x > 0) {
        int e = (blockIdx.x - 1) * 1024 + t;
        if (e < E) atomicAdd(&g_deg[ei[E + e]], 1);
        return;
    }
    {
        int out = t >> 7, k = t & 127;
        int h = out & 3;
        const float* a = (out < 4) ? a_src1 : a_dst1;
        float sum = 0.f;
#pragma unroll
        for (int c = 0; c < 16; ++c) sum = fmaf(W1[k * 64 + h * 16 + c], a[h * 16 + c], sum);
        g_v1[out * 128 + k] = sum;
    }
    if (t < 64) {
        float s2 = 0.f, d2 = 0.f;
#pragma unroll
        for (int j = 0; j < 32; ++j) {
            float wv = W2[t * 32 + j];
            s2 = fmaf(wv, a_src2[j], s2);
            d2 = fmaf(wv, a_dst2[j], d2);
        }
        g_v2s[t] = s2;
        g_v2d[t] = d2;
    }
}

// ---------------- L2: parallel per-tile scan ⊕ alphas1 = x @ v1 --------------
__global__ void k_scanblk_asad(const float* __restrict__ x, int N, int nb) {
    int t = threadIdx.x;
    if ((int)blockIdx.x < nb) {
        __shared__ int wsum[32];
        int lane = t & 31, wid = t >> 5;
        int i = blockIdx.x * 1024 + t;
        int v = (i < N) ? g_deg[i] : 0;
        if (i < N) g_deg[i] = 0;
        int xx = v;
#pragma unroll
        for (int o = 1; o < 32; o <<= 1) {
            int u = __shfl_up_sync(0xffffffffu, xx, o);
            if (lane >= o) xx += u;
        }
        if (lane == 31) wsum[wid] = xx;
        __syncthreads();
        if (wid == 0) {
            int w = wsum[lane];
#pragma unroll
            for (int o = 1; o < 32; o <<= 1) {
                int u = __shfl_up_sync(0xffffffffu, w, o);
                if (lane >= o) w += u;
            }
            wsum[lane] = w;
        }
        __syncthreads();
        int woff = (wid > 0) ? wsum[wid - 1] : 0;
        int incl = woff + xx;
        if (i < N) g_rowptr[i + 1] = incl;
        if (t == 1023) g_bsums[blockIdx.x] = incl;
        return;
    }
    int nl = t >> 3, out = t & 7;
    int n = ((int)blockIdx.x - nb) * 128 + nl;
    if (n >= N) return;
    const float4* xr = reinterpret_cast<const float4*>(&x[n * 128]);
    const float4* vr = reinterpret_cast<const float4*>(&g_v1[out * 128]);
    float sum = 0.f;
#pragma unroll
    for (int q = 0; q < 32; ++q) {
        float4 xv = __ldg(&xr[q]);
        float4 vv = vr[q];
        sum += xv.x * vv.x + xv.y * vv.y + xv.z * vv.z + xv.w * vv.w;
    }
    if (out < 4) g_as1[n * 4 + out] = sum;
    else         g_ad1[n * 4 + (out - 4)] = sum;
}

// ---------------- L2b: add tile offsets --------------------------------------
__global__ void k_scan_add(int N, int nb) {
    __shared__ int sh_off;
    int t = threadIdx.x;
    if (t < 32) {
        int lane = t;
        int v1 = (lane < nb) ? g_bsums[lane] : 0;
        int v2 = (lane + 32 < nb) ? g_bsums[lane + 32] : 0;
#pragma unroll
        for (int o = 1; o < 32; o <<= 1) {
            int u = __shfl_up_sync(0xffffffffu, v1, o);
            if (lane >= o) v1 += u;
        }
        int tot1 = __shfl_sync(0xffffffffu, v1, 31);
#pragma unroll
        for (int o = 1; o < 32; o <<= 1) {
            int u = __shfl_up_sync(0xffffffffu, v2, o);
            if (lane >= o) v2 += u;
        }
        int bid = blockIdx.x;
        int ex;
        if (bid == 0) ex = 0;
        else if (bid - 1 < 32) ex = __shfl_sync(0xffffffffu, v1, bid - 1);
        else ex = tot1 + __shfl_sync(0xffffffffu, v2, bid - 1 - 32);
        if (lane == 0) sh_off = ex;
    }
    __syncthreads();
    int off = sh_off;
    int i = blockIdx.x * 1024 + t;
    if (i < N) {
        int v = g_rowptr[i + 1] + off;
        g_rowptr[i + 1] = v;
        g_wpos[i + 1] = v;
    }
    if (blockIdx.x == 0 && t == 0) { g_rowptr[0] = 0; g_wpos[0] = 0; }
}

// ---------------- L3: CSR fill + layer-1 edge weights (standalone) -----------
__global__ void __launch_bounds__(256) k_fillw(const int* __restrict__ ei, int E) {
    int e = blockIdx.x * blockDim.x + threadIdx.x;
    if (e >= E) return;
    int src = ei[e];
    int dst = ei[E + e];
    int p = atomicAdd(&g_wpos[dst], 1);
    g_csrsrc[p] = src;
    float4 as = __ldg(reinterpret_cast<const float4*>(&g_as1[src * 4]));
    float4 ad = __ldg(reinterpret_cast<const float4*>(&g_ad1[dst * 4]));
    float4 w;
    float e0 = as.x + ad.x; w.x = __expf(fmaxf(e0, 0.2f * e0));
    float e1 = as.y + ad.y; w.y = __expf(fmaxf(e1, 0.2f * e1));
    float e2 = as.z + ad.z; w.z = __expf(fmaxf(e2, 0.2f * e2));
    float e3 = as.w + ad.w; w.w = __expf(fmaxf(e3, 0.2f * e3));
    g_w1[p] = w;
}

// ---------------- L4: GEMM1 standalone (full W cache, 40.5KB smem) -----------
__global__ void k_gemm1(const float* __restrict__ x, const float* __restrict__ W1, int N) {
    __shared__ float Wsh[128 * 64];   // 32 KB
    __shared__ float xs[128][17];
    int t = threadIdx.x;
    int n0 = blockIdx.x * 128;
    for (int i = t; i < 128 * 64; i += 256) Wsh[i] = W1[i];

    int ng = t >> 3;
    int cg = t & 7;
    float acc[4][8];
#pragma unroll
    for (int r = 0; r < 4; ++r)
#pragma unroll
        for (int j = 0; j < 8; ++j) acc[r][j] = 0.f;

    for (int kt = 0; kt < 128; kt += 16) {
        __syncthreads();
        for (int i = t; i < 128 * 16; i += 256) {
            int n = i >> 4, kk = i & 15;
            int gn = n0 + n;
            xs[n][kk] = (gn < N) ? x[gn * 128 + kt + kk] : 0.f;
        }
        __syncthreads();
#pragma unroll
        for (int kk = 0; kk < 16; ++kk) {
            float wv[8];
#pragma unroll
            for (int j = 0; j < 8; ++j) wv[j] = Wsh[(kt + kk) * 64 + cg * 8 + j];
#pragma unroll
            for (int r = 0; r < 4; ++r) {
                float xv = xs[ng * 4 + r][kk];
#pragma unroll
                for (int j = 0; j < 8; ++j) acc[r][j] = fmaf(xv, wv[j], acc[r][j]);
            }
        }
    }
#pragma unroll
    for (int r = 0; r < 4; ++r) {
        int gn = n0 + ng * 4 + r;
        if (gn < N) {
            float4* dst = reinterpret_cast<float4*>(&g_H1[gn * 64 + cg * 8]);
            dst[0] = make_float4(acc[r][0], acc[r][1], acc[r][2], acc[r][3]);
            dst[1] = make_float4(acc[r][4], acc[r][5], acc[r][6], acc[r][7]);
        }
    }
}

// ---------------- L5: layer-1 aggregation (lean) + as2/ad2 epilogue ----------
__global__ void k_agg1(const float* __restrict__ b1, int N) {
    int gw = (blockIdx.x * blockDim.x + threadIdx.x) >> 5;
    if (gw >= N) return;
    int lane = threadIdx.x & 31;
    int beg = g_rowptr[gw], end = g_rowptr[gw + 1];
    int ch = lane * 2;
    int head = ch >> 4;
    const float* w1f = reinterpret_cast<const float*>(g_w1);

    float s = 0.f, a0 = 0.f, a1 = 0.f;
    int p = beg;
    for (; p + 1 < end; p += 2) {
        int sA = g_csrsrc[p];
        int sB = g_csrsrc[p + 1];
        float wA = __ldg(&w1f[p * 4 + head]);
        float wB = __ldg(&w1f[(p + 1) * 4 + head]);
        float2 hA = *reinterpret_cast<const float2*>(&g_H1[sA * 64 + ch]);
        float2 hB = *reinterpret_cast<const float2*>(&g_H1[sB * 64 + ch]);
        s += wA;
        a0 = fmaf(wA, hA.x, a0);
        a1 = fmaf(wA, hA.y, a1);
        s += wB;
        a0 = fmaf(wB, hB.x, a0);
        a1 = fmaf(wB, hB.y, a1);
    }
    if (p < end) {
        int sA = g_csrsrc[p];
        float wA = __ldg(&w1f[p * 4 + head]);
        float2 hA = *reinterpret_cast<const float2*>(&g_H1[sA * 64 + ch]);
        s += wA;
        a0 = fmaf(wA, hA.x, a0);
        a1 = fmaf(wA, hA.y, a1);
    }
    float inv = 1.f / (s + 1e-16f);
    float o0 = fmaf(a0, inv, b1[ch]);
    float o1 = fmaf(a1, inv, b1[ch + 1]);
    o0 = (o0 > 0.f) ? o0 : expm1f(o0);   // elu
    o1 = (o1 > 0.f) ? o1 : expm1f(o1);
    *reinterpret_cast<float2*>(&g_X2[gw * 64 + ch]) = make_float2(o0, o1);

    float2 vs = *reinterpret_cast<const float2*>(&g_v2s[ch]);
    float2 vd = *reinterpret_cast<const float2*>(&g_v2d[ch]);
    float ps = o0 * vs.x + o1 * vs.y;
    float pd = o0 * vd.x + o1 * vd.y;
#pragma unroll
    for (int o = 16; o > 0; o >>= 1) {
        ps += __shfl_xor_sync(0xffffffffu, ps, o);
        pd += __shfl_xor_sync(0xffffffffu, pd, o);
    }
    if (lane == 0) { g_as2[gw] = ps; g_ad2[gw] = pd; }
}

// ---------------- L6: GEMM2 --------------------------------------------------
__global__ void k_gemm2(const float* __restrict__ W2, int N) {
    __shared__ float Wsh[16][32];
    __shared__ float xs[128][17];
    int t = threadIdx.x;
    int n0 = blockIdx.x * 128;
    int ng = t >> 2;
    int cg = t & 3;
    float acc[2][8];
#pragma unroll
    for (int r = 0; r < 2; ++r)
#pragma unroll
        for (int j = 0; j < 8; ++j) acc[r][j] = 0.f;

    for (int kt = 0; kt < 64; kt += 16) {
        __syncthreads();
        for (int i = t; i < 16 * 32; i += 256) Wsh[i >> 5][i & 31] = W2[(kt + (i >> 5)) * 32 + (i & 31)];
        for (int i = t; i < 128 * 16; i += 256) {
            int n = i >> 4, kk = i & 15;
            int gn = n0 + n;
            xs[n][kk] = (gn < N) ? g_X2[gn * 64 + kt + kk] : 0.f;
        }
        __syncthreads();
#pragma unroll
        for (int kk = 0; kk < 16; ++kk) {
            float wv[8];
#pragma unroll
            for (int j = 0; j < 8; ++j) wv[j] = Wsh[kk][cg * 8 + j];
#pragma unroll
            for (int r = 0; r < 2; ++r) {
                float xv = xs[ng * 2 + r][kk];
#pragma unroll
                for (int j = 0; j < 8; ++j) acc[r][j] = fmaf(xv, wv[j], acc[r][j]);
            }
        }
    }
#pragma unroll
    for (int r = 0; r < 2; ++r) {
        int gn = n0 + ng * 2 + r;
        if (gn < N) {
            float4* dst = reinterpret_cast<float4*>(&g_H2[gn * 32 + cg * 8]);
            dst[0] = make_float4(acc[r][0], acc[r][1], acc[r][2], acc[r][3]);
            dst[1] = make_float4(acc[r][4], acc[r][5], acc[r][6], acc[r][7]);
        }
    }
}

// ---------------- L7: layer-2 aggregation with inline w2 ---------------------
__global__ void k_agg2(const float* __restrict__ b2, float* __restrict__ out, int N) {
    int gw = (blockIdx.x * blockDim.x + threadIdx.x) >> 5;
    if (gw >= N) return;
    int lane = threadIdx.x & 31;
    int beg = g_rowptr[gw], end = g_rowptr[gw + 1];
    float adv = g_ad2[gw];

    float s = 0.f, a = 0.f;
    int p = beg;
    for (; p + 1 < end; p += 2) {
        int sA = g_csrsrc[p];
        int sB = g_csrsrc[p + 1];
        float eA = __ldg(&g_as2[sA]) + adv;
        float eB = __ldg(&g_as2[sB]) + adv;
        float hA = g_H2[sA * 32 + lane];
        float hB = g_H2[sB * 32 + lane];
        float wA = __expf(fmaxf(eA, 0.2f * eA));
        float wB = __expf(fmaxf(eB, 0.2f * eB));
        s += wA;
        a = fmaf(wA, hA, a);
        s += wB;
        a = fmaf(wB, hB, a);
    }
    if (p < end) {
        int sA = g_csrsrc[p];
        float eA = __ldg(&g_as2[sA]) + adv;
        float hA = g_H2[sA * 32 + lane];
        float wA = __expf(fmaxf(eA, 0.2f * eA));
        s += wA;
        a = fmaf(wA, hA, a);
    }
    float inv = 1.f / (s + 1e-16f);
    out[gw * 32 + lane] = fmaf(a, inv, b2[lane]);
}

// ---------------- launch -----------------------------------------------------
extern "C" void kernel_launch(void* const* d_in, const int* in_sizes, int n_in,
                              void* d_out, int out_size) {
    const float* x      = (const float*)d_in[0];
    const int*   ei     = (const int*)  d_in[1];
    const float* W1     = (const float*)d_in[2];
    const float* a_src1 = (const float*)d_in[3];
    const float* a_dst1 = (const float*)d_in[4];
    const float* b1     = (const float*)d_in[5];
    const float* W2     = (const float*)d_in[6];
    const float* a_src2 = (const float*)d_in[7];
    const float* a_dst2 = (const float*)d_in[8];
    const float* b2     = (const float*)d_in[9];

    int N = in_sizes[0] / 128;
    int E = in_sizes[1] / 2;
    int nb = (N + 1023) / 1024;
    int asadBlocks = (N + 127) / 128;

    // L1: tiny projections (block 0) + degree histogram
    k_pre_hist<<<1 + (E + 1023) / 1024, 1024>>>(W1, a_src1, a_dst1, W2, a_src2, a_dst2, ei, E);
    // L2: parallel per-tile scan + alphas1 = x @ v1
    k_scanblk_asad<<<nb + asadBlocks, 1024>>>(x, N, nb);
    // L2b: add tile offsets (also writes wpos)
    k_scan_add<<<nb, 1024>>>(N, nb);
    // L3: CSR fill + layer-1 edge weights (full occupancy, standalone)
    k_fillw<<<(E + 255) / 256, 256>>>(ei, E);
    // L4: GEMM1 (standalone, full W cache)
    k_gemm1<<<(N + 127) / 128, 256>>>(x, W1, N);
    // L5: layer-1 aggregation (+elu, +as2/ad2)
    k_agg1<<<(N * 32 + 255) / 256, 256>>>(b1, N);
    // L6: GEMM2
    k_gemm2<<<(N + 127) / 128, 256>>>(W2, N);
    // L7: layer-2 aggregation (inline w2)
    k_agg2<<<(N * 32 + 255) / 256, 256>>>(b2, (float*)d_out, N);
}

// round 9
// speedup vs baseline: 1.3696x; 1.3696x over previous
#include <cuda_runtime.h>

// ---------------- static scratch (no dynamic allocation allowed) ------------
#define MAXN 50016
#define MAXE 800000

__device__ float g_H1[MAXN * 64];   // layer-1 features x@W1
__device__ float g_as1[MAXN * 4];   // alpha_src layer1 per head
__device__ float g_ad1[MAXN * 4];   // alpha_dst layer1 per head
__device__ float g_X2[MAXN * 64];   // elu(gat1 output) = input to layer2
__device__ float g_H2[MAXN * 32];   // layer-2 features X2@W2
__device__ float g_as2[MAXN];
__device__ float g_ad2[MAXN];
__device__ int   g_deg[MAXN];       // zero at load; re-zeroed by k_scan_add each run
__device__ int   g_rowptr[MAXN + 1];
__device__ int   g_wpos[MAXN + 1];
__device__ int   g_csrsrc[MAXE];
__device__ int   g_bsums[64];

// ---------------- L1: fused GEMM1 (+alpha epilogue) ⊕ edge histogram --------
// gemm blocks: 256 threads, tile = 128 nodes, thread = 4 nodes x 8 cols.
// hist blocks: grid-stride atomicAdd over dst.
__global__ void k_gemm1_hist(const float* __restrict__ x, const float* __restrict__ W1,
                             const float* __restrict__ a_src, const float* __restrict__ a_dst,
                             const int* __restrict__ ei, int N, int E, int gemmBlocks) {
    __shared__ float Wsh[128 * 64];   // 32 KB
    __shared__ float xs[128][17];     // 16-wide k tile + pad

    if (blockIdx.x >= gemmBlocks) {
        // ---- histogram part (independent of GEMM) ----
        int nb = gridDim.x - gemmBlocks;
        int stride = nb * blockDim.x;
        for (int e = (blockIdx.x - gemmBlocks) * blockDim.x + threadIdx.x; e < E; e += stride)
            atomicAdd(&g_deg[ei[E + e]], 1);
        return;
    }

    int t = threadIdx.x;
    int n0 = blockIdx.x * 128;
    for (int i = t; i < 128 * 64; i += 256) Wsh[i] = W1[i];

    int ng = t >> 3;   // 0..31 node group (4 nodes each)
    int cg = t & 7;    // 0..7 col group (8 cols each)
    float acc[4][8];
#pragma unroll
    for (int r = 0; r < 4; ++r)
#pragma unroll
        for (int j = 0; j < 8; ++j) acc[r][j] = 0.f;

    for (int kt = 0; kt < 128; kt += 16) {
        __syncthreads();
        for (int i = t; i < 128 * 16; i += 256) {
            int n = i >> 4, kk = i & 15;
            int gn = n0 + n;
            xs[n][kk] = (gn < N) ? x[gn * 128 + kt + kk] : 0.f;
        }
        __syncthreads();
#pragma unroll
        for (int kk = 0; kk < 16; ++kk) {
            float wv[8];
#pragma unroll
            for (int j = 0; j < 8; ++j) wv[j] = Wsh[(kt + kk) * 64 + cg * 8 + j];
#pragma unroll
            for (int r = 0; r < 4; ++r) {
                float xv = xs[ng * 4 + r][kk];
#pragma unroll
                for (int j = 0; j < 8; ++j) acc[r][j] = fmaf(xv, wv[j], acc[r][j]);
            }
        }
    }

    // per-thread attention coefficient slices
    float asw[8], adw[8];
#pragma unroll
    for (int j = 0; j < 8; ++j) { asw[j] = __ldg(&a_src[cg * 8 + j]); adw[j] = __ldg(&a_dst[cg * 8 + j]); }

#pragma unroll
    for (int r = 0; r < 4; ++r) {
        int gn = n0 + ng * 4 + r;
        float ps = 0.f, pd = 0.f;
#pragma unroll
        for (int j = 0; j < 8; ++j) { ps = fmaf(acc[r][j], asw[j], ps); pd = fmaf(acc[r][j], adw[j], pd); }
        // combine the two col-groups of this head (lanes t, t^1)
        ps += __shfl_xor_sync(0xffffffffu, ps, 1);
        pd += __shfl_xor_sync(0xffffffffu, pd, 1);
        if (gn < N) {
            float4* dst = reinterpret_cast<float4*>(&g_H1[gn * 64 + cg * 8]);
            dst[0] = make_float4(acc[r][0], acc[r][1], acc[r][2], acc[r][3]);
            dst[1] = make_float4(acc[r][4], acc[r][5], acc[r][6], acc[r][7]);
            if ((cg & 1) == 0) {
                g_as1[gn * 4 + (cg >> 1)] = ps;
                g_ad1[gn * 4 + (cg >> 1)] = pd;
            }
        }
    }
}

// ---------------- CSR scan (per-tile) ----------------------------------------
__global__ void k_scan_block(int N) {
    __shared__ int sh[1024];
    int t = threadIdx.x;
    int i = blockIdx.x * 1024 + t;
    int v = (i < N) ? g_deg[i] : 0;
    sh[t] = v;
    __syncthreads();
    for (int off = 1; off < 1024; off <<= 1) {
        int u = (t >= off) ? sh[t - off] : 0;
        __syncthreads();
        sh[t] += u;
        __syncthreads();
    }
    if (i < N) g_rowptr[i + 1] = sh[t];
    if (t == 1023) g_bsums[blockIdx.x] = sh[1023];
}

// ---------------- CSR scan: add tile offsets (warp-scans bsums per block) ----
__global__ void k_scan_add(int N, int nb) {
    __shared__ int sh_off;
    int t = threadIdx.x;
    if (t < 32) {
        int lane = t;
        int v1 = (lane < nb) ? g_bsums[lane] : 0;
        int v2 = (lane + 32 < nb) ? g_bsums[lane + 32] : 0;
#pragma unroll
        for (int o = 1; o < 32; o <<= 1) {
            int u = __shfl_up_sync(0xffffffffu, v1, o);
            if (lane >= o) v1 += u;
        }
        int tot1 = __shfl_sync(0xffffffffu, v1, 31);
#pragma unroll
        for (int o = 1; o < 32; o <<= 1) {
            int u = __shfl_up_sync(0xffffffffu, v2, o);
            if (lane >= o) v2 += u;
        }
        int bid = blockIdx.x;
        int ex;
        if (bid == 0) ex = 0;
        else if (bid - 1 < 32) ex = __shfl_sync(0xffffffffu, v1, bid - 1);
        else ex = tot1 + __shfl_sync(0xffffffffu, v2, bid - 1 - 32);
        if (lane == 0) sh_off = ex;
    }
    __syncthreads();
    int off = sh_off;
    int i = blockIdx.x * 1024 + t;
    if (i < N) {
        int v = g_rowptr[i + 1] + off;
        g_rowptr[i + 1] = v;
        g_wpos[i + 1] = v;
        g_deg[i] = 0;                  // reset for next replay
    }
    if (blockIdx.x == 0 && t == 0) { g_rowptr[0] = 0; g_wpos[0] = 0; }
}

// ---------------- CSR fill ----------------------------------------------------
__global__ void k_fill(const int* __restrict__ ei, int E) {
    int e = blockIdx.x * blockDim.x + threadIdx.x;
    if (e < E) {
        int src = ei[e];
        int dst = ei[E + e];
        int p = atomicAdd(&g_wpos[dst], 1);
        g_csrsrc[p] = src;
    }
}

// ---------------- layer-1 aggregation: warp/node, no-max softmax -------------
// e = leakyrelu(as+ad) is O(1) (0.1-scaled attention vectors), so exp cannot
// overflow; the softmax ratio without max subtraction is mathematically equal.
__global__ void k_agg1(const float* __restrict__ b1, int N) {
    int gw = (blockIdx.x * blockDim.x + threadIdx.x) >> 5;
    if (gw >= N) return;
    int lane = threadIdx.x & 31;
    int beg = g_rowptr[gw], end = g_rowptr[gw + 1];
    int ch = lane * 2;
    int head = ch >> 4;
    float adv = g_ad1[gw * 4 + head];

    float s = 0.f, a0 = 0.f, a1 = 0.f;
    int srcN = 0; float asvN = 0.f; float2 hvN = make_float2(0.f, 0.f);
    if (beg < end) {
        srcN = g_csrsrc[beg];
        asvN = __ldg(&g_as1[srcN * 4 + head]);
        hvN = *reinterpret_cast<const float2*>(&g_H1[srcN * 64 + ch]);
    }
    for (int p = beg; p < end; ++p) {
        float asv = asvN; float2 hv = hvN;
        if (p + 1 < end) {
            srcN = g_csrsrc[p + 1];
            asvN = __ldg(&g_as1[srcN * 4 + head]);
            hvN = *reinterpret_cast<const float2*>(&g_H1[srcN * 64 + ch]);
        }
        float e = asv + adv;
        e = fmaxf(e, 0.2f * e);          // leaky_relu
        float w = __expf(e);
        s += w;
        a0 = fmaf(w, hv.x, a0);
        a1 = fmaf(w, hv.y, a1);
    }
    float inv = 1.f / (s + 1e-16f);
    float o0 = fmaf(a0, inv, b1[ch]);
    float o1 = fmaf(a1, inv, b1[ch + 1]);
    o0 = (o0 > 0.f) ? o0 : expm1f(o0);   // elu
    o1 = (o1 > 0.f) ? o1 : expm1f(o1);
    *reinterpret_cast<float2*>(&g_X2[gw * 64 + ch]) = make_float2(o0, o1);
}

// ---------------- GEMM 2: H2 = X2[N,64] @ W2[64,32] (+alpha epilogue) --------
__global__ void k_gemm2(const float* __restrict__ W2,
                        const float* __restrict__ a_src, const float* __restrict__ a_dst, int N) {
    __shared__ float Wsh[64 * 32];    // 8 KB
    __shared__ float xs[128][65];     // full 64-wide k, padded
    int t = threadIdx.x;
    int n0 = blockIdx.x * 128;
    for (int i = t; i < 64 * 32; i += 128) Wsh[i] = W2[i];
    for (int i = t; i < 128 * 64; i += 128) {
        int n = i >> 6, k = i & 63;
        int gn = n0 + n;
        xs[n][k] = (gn < N) ? g_X2[gn * 64 + k] : 0.f;
    }
    __syncthreads();
    int ng = t >> 2;   // 0..31 (4 nodes each)
    int cg = t & 3;    // 0..3 (8 cols each)
    float acc[4][8];
#pragma unroll
    for (int r = 0; r < 4; ++r)
#pragma unroll
        for (int j = 0; j < 8; ++j) acc[r][j] = 0.f;
#pragma unroll 4
    for (int k = 0; k < 64; ++k) {
        float wv[8];
#pragma unroll
        for (int j = 0; j < 8; ++j) wv[j] = Wsh[k * 32 + cg * 8 + j];
#pragma unroll
        for (int r = 0; r < 4; ++r) {
            float xv = xs[ng * 4 + r][k];
#pragma unroll
            for (int j = 0; j < 8; ++j) acc[r][j] = fmaf(xv, wv[j], acc[r][j]);
        }
    }

    float asw[8], adw[8];
#pragma unroll
    for (int j = 0; j < 8; ++j) { asw[j] = __ldg(&a_src[cg * 8 + j]); adw[j] = __ldg(&a_dst[cg * 8 + j]); }

#pragma unroll
    for (int r = 0; r < 4; ++r) {
        int gn = n0 + ng * 4 + r;
        float ps = 0.f, pd = 0.f;
#pragma unroll
        for (int j = 0; j < 8; ++j) { ps = fmaf(acc[r][j], asw[j], ps); pd = fmaf(acc[r][j], adw[j], pd); }
        ps += __shfl_xor_sync(0xffffffffu, ps, 1);
        pd += __shfl_xor_sync(0xffffffffu, pd, 1);
        ps += __shfl_xor_sync(0xffffffffu, ps, 2);
        pd += __shfl_xor_sync(0xffffffffu, pd, 2);
        if (gn < N) {
            float4* dst = reinterpret_cast<float4*>(&g_H2[gn * 32 + cg * 8]);
            dst[0] = make_float4(acc[r][0], acc[r][1], acc[r][2], acc[r][3]);
            dst[1] = make_float4(acc[r][4], acc[r][5], acc[r][6], acc[r][7]);
            if (cg == 0) { g_as2[gn] = ps; g_ad2[gn] = pd; }
        }
    }
}

// ---------------- layer-2 aggregation: warp/node, no-max softmax -------------
__global__ void k_agg2(const float* __restrict__ b2, float* __restrict__ out, int N) {
    int gw = (blockIdx.x * blockDim.x + threadIdx.x) >> 5;
    if (gw >= N) return;
    int lane = threadIdx.x & 31;
    int beg = g_rowptr[gw], end = g_rowptr[gw + 1];
    float adv = g_ad2[gw];

    float s = 0.f, a = 0.f;
    int srcN = 0; float asvN = 0.f; float hvN = 0.f;
    if (beg < end) {
        srcN = g_csrsrc[beg];
        asvN = __ldg(&g_as2[srcN]);
        hvN = g_H2[srcN * 32 + lane];
    }
    for (int p = beg; p < end; ++p) {
        float asv = asvN; float hv = hvN;
        if (p + 1 < end) {
            srcN = g_csrsrc[p + 1];
            asvN = __ldg(&g_as2[srcN]);
            hvN = g_H2[srcN * 32 + lane];
        }
        float e = asv + adv;
        e = fmaxf(e, 0.2f * e);          // leaky_relu
        float w = __expf(e);
        s += w;
        a = fmaf(w, hv, a);
    }
    float inv = 1.f / (s + 1e-16f);
    out[gw * 32 + lane] = fmaf(a, inv, b2[lane]);
}

// ---------------- launch -----------------------------------------------------
extern "C" void kernel_launch(void* const* d_in, const int* in_sizes, int n_in,
                              void* d_out, int out_size) {
    const float* x      = (const float*)d_in[0];
    const int*   ei     = (const int*)  d_in[1];
    const float* W1     = (const float*)d_in[2];
    const float* a_src1 = (const float*)d_in[3];
    const float* a_dst1 = (const float*)d_in[4];
    const float* b1     = (const float*)d_in[5];
    const float* W2     = (const float*)d_in[6];
    const float* a_src2 = (const float*)d_in[7];
    const float* a_dst2 = (const float*)d_in[8];
    const float* b2     = (const float*)d_in[9];

    int N = in_sizes[0] / 128;
    int E = in_sizes[1] / 2;
    int nb = (N + 1023) / 1024;

    int gemmBlocks = (N + 127) / 128;
    int histBlocks = 1184;

    // L1: GEMM1(+alphas1) overlapped with edge histogram (independent work)
    k_gemm1_hist<<<gemmBlocks + histBlocks, 256>>>(x, W1, a_src1, a_dst1, ei, N, E, gemmBlocks);
    // CSR scan (2 kernels) + fill
    k_scan_block<<<nb, 1024>>>(N);
    k_scan_add<<<nb, 1024>>>(N, nb);   // also resets g_deg
    k_fill<<<(E + 255) / 256, 256>>>(ei, E);
    // layer 1 aggregation (+elu)
    k_agg1<<<(N * 32 + 255) / 256, 256>>>(b1, N);
    // layer 2
    k_gemm2<<<(N + 127) / 128, 128>>>(W2, a_src2, a_dst2, N);
    k_agg2<<<(N * 32 + 255) / 256, 256>>>(b2, (float*)d_out, N);
}

// round 10
// speedup vs baseline: 1.5185x; 1.1087x over previous
#include <cuda_runtime.h>

// ---------------- static scratch (no dynamic allocation allowed) ------------
#define MAXN 50016
#define MAXE 800000

__device__ float g_H1[MAXN * 64];   // layer-1 features x@W1
__device__ float g_as1[MAXN * 4];   // alpha_src layer1 per head
__device__ float g_ad1[MAXN * 4];   // alpha_dst layer1 per head
__device__ float g_X2[MAXN * 64];   // elu(gat1 output) = input to layer2
__device__ float g_H2[MAXN * 32];   // layer-2 features X2@W2
__device__ float g_as2[MAXN];
__device__ float g_ad2[MAXN];
__device__ int   g_deg[MAXN];       // zero at load; re-zeroed by k_scan_add each run
__device__ int   g_rowptr[MAXN + 1];
__device__ int   g_wpos[MAXN + 1];
__device__ int   g_csrsrc[MAXE];
__device__ float4 g_w1[MAXE];       // layer-1 edge weights (4 heads), CSR order
__device__ int   g_bsums[64];
__device__ float g_v2s[64];         // W2@a_src2 (computed in gemm2 path epilogue inputs)
__device__ float g_v2d[64];         // W2@a_dst2

// ---------------- L1: fused GEMM1 (+alpha epilogue) ⊕ edge histogram --------
__global__ void k_gemm1_hist(const float* __restrict__ x, const float* __restrict__ W1,
                             const float* __restrict__ a_src, const float* __restrict__ a_dst,
                             const int* __restrict__ ei, int N, int E, int gemmBlocks) {
    __shared__ float Wsh[128 * 64];   // 32 KB
    __shared__ float xs[128][17];     // 16-wide k tile + pad

    if (blockIdx.x >= gemmBlocks) {
        int nb = gridDim.x - gemmBlocks;
        int stride = nb * blockDim.x;
        for (int e = (blockIdx.x - gemmBlocks) * blockDim.x + threadIdx.x; e < E; e += stride)
            atomicAdd(&g_deg[ei[E + e]], 1);
        return;
    }

    int t = threadIdx.x;
    int n0 = blockIdx.x * 128;
    for (int i = t; i < 128 * 64; i += 256) Wsh[i] = W1[i];

    int ng = t >> 3;   // 0..31 node group (4 nodes each)
    int cg = t & 7;    // 0..7 col group (8 cols each)
    float acc[4][8];
#pragma unroll
    for (int r = 0; r < 4; ++r)
#pragma unroll
        for (int j = 0; j < 8; ++j) acc[r][j] = 0.f;

    for (int kt = 0; kt < 128; kt += 16) {
        __syncthreads();
        for (int i = t; i < 128 * 16; i += 256) {
            int n = i >> 4, kk = i & 15;
            int gn = n0 + n;
            xs[n][kk] = (gn < N) ? x[gn * 128 + kt + kk] : 0.f;
        }
        __syncthreads();
#pragma unroll
        for (int kk = 0; kk < 16; ++kk) {
            float wv[8];
#pragma unroll
            for (int j = 0; j < 8; ++j) wv[j] = Wsh[(kt + kk) * 64 + cg * 8 + j];
#pragma unroll
            for (int r = 0; r < 4; ++r) {
                float xv = xs[ng * 4 + r][kk];
#pragma unroll
                for (int j = 0; j < 8; ++j) acc[r][j] = fmaf(xv, wv[j], acc[r][j]);
            }
        }
    }

    float asw[8], adw[8];
#pragma unroll
    for (int j = 0; j < 8; ++j) { asw[j] = __ldg(&a_src[cg * 8 + j]); adw[j] = __ldg(&a_dst[cg * 8 + j]); }

#pragma unroll
    for (int r = 0; r < 4; ++r) {
        int gn = n0 + ng * 4 + r;
        float ps = 0.f, pd = 0.f;
#pragma unroll
        for (int j = 0; j < 8; ++j) { ps = fmaf(acc[r][j], asw[j], ps); pd = fmaf(acc[r][j], adw[j], pd); }
        ps += __shfl_xor_sync(0xffffffffu, ps, 1);
        pd += __shfl_xor_sync(0xffffffffu, pd, 1);
        if (gn < N) {
            float4* dst = reinterpret_cast<float4*>(&g_H1[gn * 64 + cg * 8]);
            dst[0] = make_float4(acc[r][0], acc[r][1], acc[r][2], acc[r][3]);
            dst[1] = make_float4(acc[r][4], acc[r][5], acc[r][6], acc[r][7]);
            if ((cg & 1) == 0) {
                g_as1[gn * 4 + (cg >> 1)] = ps;
                g_ad1[gn * 4 + (cg >> 1)] = pd;
            }
        }
    }
}

// ---------------- CSR scan (per-tile) ----------------------------------------
__global__ void k_scan_block(int N) {
    __shared__ int sh[1024];
    int t = threadIdx.x;
    int i = blockIdx.x * 1024 + t;
    int v = (i < N) ? g_deg[i] : 0;
    sh[t] = v;
    __syncthreads();
    for (int off = 1; off < 1024; off <<= 1) {
        int u = (t >= off) ? sh[t - off] : 0;
        __syncthreads();
        sh[t] += u;
        __syncthreads();
    }
    if (i < N) g_rowptr[i + 1] = sh[t];
    if (t == 1023) g_bsums[blockIdx.x] = sh[1023];
}

// ---------------- CSR scan: add tile offsets ---------------------------------
__global__ void k_scan_add(int N, int nb) {
    __shared__ int sh_off;
    int t = threadIdx.x;
    if (t < 32) {
        int lane = t;
        int v1 = (lane < nb) ? g_bsums[lane] : 0;
        int v2 = (lane + 32 < nb) ? g_bsums[lane + 32] : 0;
#pragma unroll
        for (int o = 1; o < 32; o <<= 1) {
            int u = __shfl_up_sync(0xffffffffu, v1, o);
            if (lane >= o) v1 += u;
        }
        int tot1 = __shfl_sync(0xffffffffu, v1, 31);
#pragma unroll
        for (int o = 1; o < 32; o <<= 1) {
            int u = __shfl_up_sync(0xffffffffu, v2, o);
            if (lane >= o) v2 += u;
        }
        int bid = blockIdx.x;
        int ex;
        if (bid == 0) ex = 0;
        else if (bid - 1 < 32) ex = __shfl_sync(0xffffffffu, v1, bid - 1);
        else ex = tot1 + __shfl_sync(0xffffffffu, v2, bid - 1 - 32);
        if (lane == 0) sh_off = ex;
    }
    __syncthreads();
    int off = sh_off;
    int i = blockIdx.x * 1024 + t;
    if (i < N) {
        int v = g_rowptr[i + 1] + off;
        g_rowptr[i + 1] = v;
        g_wpos[i + 1] = v;
        g_deg[i] = 0;
    }
    if (blockIdx.x == 0 && t == 0) { g_rowptr[0] = 0; g_wpos[0] = 0; }
}

// ---------------- CSR fill + layer-1 edge weights ----------------------------
__global__ void __launch_bounds__(256) k_fillw(const int* __restrict__ ei, int E) {
    int e = blockIdx.x * blockDim.x + threadIdx.x;
    if (e >= E) return;
    int src = ei[e];
    int dst = ei[E + e];
    int p = atomicAdd(&g_wpos[dst], 1);
    g_csrsrc[p] = src;
    float4 as = __ldg(reinterpret_cast<const float4*>(&g_as1[src * 4]));
    float4 ad = __ldg(reinterpret_cast<const float4*>(&g_ad1[dst * 4]));
    float4 w;
    float e0 = as.x + ad.x; w.x = __expf(fmaxf(e0, 0.2f * e0));
    float e1 = as.y + ad.y; w.y = __expf(fmaxf(e1, 0.2f * e1));
    float e2 = as.z + ad.z; w.z = __expf(fmaxf(e2, 0.2f * e2));
    float e3 = as.w + ad.w; w.w = __expf(fmaxf(e3, 0.2f * e3));
    g_w1[p] = w;
}

// ---------------- layer-1 aggregation: HALF-WARP per node, precomputed w -----
// lanes 0-15 -> node 2*warp, lanes 16-31 -> node 2*warp+1.
// each lane covers 4 channels (float4); head = hl>>2.
__global__ void k_agg1(const float* __restrict__ b1,
                       const float* __restrict__ a_src2, const float* __restrict__ a_dst2,
                       const float* __restrict__ W2, int N) {
    int warp = (blockIdx.x * blockDim.x + threadIdx.x) >> 5;
    int lane = threadIdx.x & 31;
    int half = lane >> 4;
    int hl = lane & 15;
    int node = warp * 2 + half;
    if (node >= N) return;
    int beg = g_rowptr[node], end = g_rowptr[node + 1];
    int ch = hl * 4;
    int head = hl >> 2;
    const float* w1f = reinterpret_cast<const float*>(g_w1);

    float s = 0.f, a0 = 0.f, a1 = 0.f, a2 = 0.f, a3 = 0.f;
    for (int p = beg; p < end; ++p) {
        int src = g_csrsrc[p];
        float w = __ldg(&w1f[p * 4 + head]);
        float4 h = *reinterpret_cast<const float4*>(&g_H1[src * 64 + ch]);
        s += w;
        a0 = fmaf(w, h.x, a0);
        a1 = fmaf(w, h.y, a1);
        a2 = fmaf(w, h.z, a2);
        a3 = fmaf(w, h.w, a3);
    }
    float inv = 1.f / (s + 1e-16f);
    float4 bb = *reinterpret_cast<const float4*>(&b1[ch]);
    float o0 = fmaf(a0, inv, bb.x);
    float o1 = fmaf(a1, inv, bb.y);
    float o2 = fmaf(a2, inv, bb.z);
    float o3 = fmaf(a3, inv, bb.w);
    o0 = (o0 > 0.f) ? o0 : expm1f(o0);   // elu
    o1 = (o1 > 0.f) ? o1 : expm1f(o1);
    o2 = (o2 > 0.f) ? o2 : expm1f(o2);
    o3 = (o3 > 0.f) ? o3 : expm1f(o3);
    *reinterpret_cast<float4*>(&g_X2[node * 64 + ch]) = make_float4(o0, o1, o2, o3);

    // epilogue: as2/ad2 = X2row . (W2@a2) ; v2 vectors precomputed by k_gemm2? No —
    // compute v2 on the fly: v2s[ch+i] = sum_j W2[(ch+i)*32+j]*a_src2[j] is 32 FMA x4.
    // Cheaper: use g_v2s/g_v2d filled by k_vpre (tiny kernel below).
    float4 vs = *reinterpret_cast<const float4*>(&g_v2s[ch]);
    float4 vd = *reinterpret_cast<const float4*>(&g_v2d[ch]);
    float ps = o0 * vs.x + o1 * vs.y + o2 * vs.z + o3 * vs.w;
    float pd = o0 * vd.x + o1 * vd.y + o2 * vd.z + o3 * vd.w;
#pragma unroll
    for (int o = 1; o < 16; o <<= 1) {
        ps += __shfl_xor_sync(0xffffffffu, ps, o);
        pd += __shfl_xor_sync(0xffffffffu, pd, o);
    }
    if (hl == 0) { g_as2[node] = ps; g_ad2[node] = pd; }
}

// ---------------- tiny: v2 = W2 @ a2 (64 threads, fused into scan_add grid? no, 1 block)
__global__ void k_vpre(const float* __restrict__ W2,
                       const float* __restrict__ a_src2, const float* __restrict__ a_dst2) {
    int t = threadIdx.x;
    if (t < 64) {
        float s2 = 0.f, d2 = 0.f;
#pragma unroll
        for (int j = 0; j < 32; ++j) {
            float wv = W2[t * 32 + j];
            s2 = fmaf(wv, a_src2[j], s2);
            d2 = fmaf(wv, a_dst2[j], d2);
        }
        g_v2s[t] = s2;
        g_v2d[t] = d2;
    }
}

// ---------------- GEMM 2: H2 = X2[N,64] @ W2[64,32] --------------------------
__global__ void k_gemm2(const float* __restrict__ W2, int N) {
    __shared__ float Wsh[64 * 32];    // 8 KB
    __shared__ float xs[128][65];     // full 64-wide k, padded
    int t = threadIdx.x;
    int n0 = blockIdx.x * 128;
    for (int i = t; i < 64 * 32; i += 128) Wsh[i] = W2[i];
    for (int i = t; i < 128 * 64; i += 128) {
        int n = i >> 6, k = i & 63;
        int gn = n0 + n;
        xs[n][k] = (gn < N) ? g_X2[gn * 64 + k] : 0.f;
    }
    __syncthreads();
    int ng = t >> 2;
    int cg = t & 3;
    float acc[4][8];
#pragma unroll
    for (int r = 0; r < 4; ++r)
#pragma unroll
        for (int j = 0; j < 8; ++j) acc[r][j] = 0.f;
#pragma unroll 4
    for (int k = 0; k < 64; ++k) {
        float wv[8];
#pragma unroll
        for (int j = 0; j < 8; ++j) wv[j] = Wsh[k * 32 + cg * 8 + j];
#pragma unroll
        for (int r = 0; r < 4; ++r) {
            float xv = xs[ng * 4 + r][k];
#pragma unroll
            for (int j = 0; j < 8; ++j) acc[r][j] = fmaf(xv, wv[j], acc[r][j]);
        }
    }
#pragma unroll
    for (int r = 0; r < 4; ++r) {
        int gn = n0 + ng * 4 + r;
        if (gn < N) {
            float4* dst = reinterpret_cast<float4*>(&g_H2[gn * 32 + cg * 8]);
            dst[0] = make_float4(acc[r][0], acc[r][1], acc[r][2], acc[r][3]);
            dst[1] = make_float4(acc[r][4], acc[r][5], acc[r][6], acc[r][7]);
        }
    }
}

// ---------------- layer-2 aggregation: HALF-WARP per node, inline w ----------
__global__ void k_agg2(const float* __restrict__ b2, float* __restrict__ out, int N) {
    int warp = (blockIdx.x * blockDim.x + threadIdx.x) >> 5;
    int lane = threadIdx.x & 31;
    int half = lane >> 4;
    int hl = lane & 15;
    int node = warp * 2 + half;
    if (node >= N) return;
    int beg = g_rowptr[node], end = g_rowptr[node + 1];
    int ch = hl * 2;
    float adv = g_ad2[node];

    float s = 0.f, a0 = 0.f, a1 = 0.f;
    for (int p = beg; p < end; ++p) {
        int src = g_csrsrc[p];
        float e = __ldg(&g_as2[src]) + adv;
        float2 h = *reinterpret_cast<const float2*>(&g_H2[src * 32 + ch]);
        float w = __expf(fmaxf(e, 0.2f * e));
        s += w;
        a0 = fmaf(w, h.x, a0);
        a1 = fmaf(w, h.y, a1);
    }
    float inv = 1.f / (s + 1e-16f);
    float2 bb = *reinterpret_cast<const float2*>(&b2[ch]);
    float2 o;
    o.x = fmaf(a0, inv, bb.x);
    o.y = fmaf(a1, inv, bb.y);
    *reinterpret_cast<float2*>(&out[node * 32 + ch]) = o;
}

// ---------------- launch -----------------------------------------------------
extern "C" void kernel_launch(void* const* d_in, const int* in_sizes, int n_in,
                              void* d_out, int out_size) {
    const float* x      = (const float*)d_in[0];
    const int*   ei     = (const int*)  d_in[1];
    const float* W1     = (const float*)d_in[2];
    const float* a_src1 = (const float*)d_in[3];
    const float* a_dst1 = (const float*)d_in[4];
    const float* b1     = (const float*)d_in[5];
    const float* W2     = (const float*)d_in[6];
    const float* a_src2 = (const float*)d_in[7];
    const float* a_dst2 = (const float*)d_in[8];
    const float* b2     = (const float*)d_in[9];

    int N = in_sizes[0] / 128;
    int E = in_sizes[1] / 2;
    int nb = (N + 1023) / 1024;

    int gemmBlocks = (N + 127) / 128;
    int histBlocks = 1184;
    int aggWarps = (N + 1) / 2;          // 2 nodes per warp

    // L1: GEMM1(+alphas1) overlapped with edge histogram
    k_gemm1_hist<<<gemmBlocks + histBlocks, 256>>>(x, W1, a_src1, a_dst1, ei, N, E, gemmBlocks);
    // tiny v2 projection (independent; overlaps the stream tail trivially)
    k_vpre<<<1, 64>>>(W2, a_src2, a_dst2);
    // CSR scan (2 kernels) + fill(+w1)
    k_scan_block<<<nb, 1024>>>(N);
    k_scan_add<<<nb, 1024>>>(N, nb);
    k_fillw<<<(E + 255) / 256, 256>>>(ei, E);
    // layer 1 aggregation (+elu, +as2/ad2)
    k_agg1<<<(aggWarps * 32 + 255) / 256, 256>>>(b1, a_src2, a_dst2, W2, N);
    // layer 2
    k_gemm2<<<(N + 127) / 128, 128>>>(W2, N);
    k_agg2<<<(aggWarps * 32 + 255) / 256, 256>>>(b2, (float*)d_out, N);
}

// round 11
// speedup vs baseline: 1.5467x; 1.0186x over previous
#include <cuda_runtime.h>

// ---------------- static scratch (no dynamic allocation allowed) ------------
#define MAXN 50016
#define MAXE 800000

__device__ float g_H1[MAXN * 64];   // layer-1 features x@W1
__device__ float g_as1[MAXN * 4];   // alpha_src layer1 per head
__device__ float g_ad1[MAXN * 4];   // alpha_dst layer1 per head
__device__ float g_X2[MAXN * 64];   // elu(gat1 output) = input to layer2
__device__ float g_H2[MAXN * 32];   // layer-2 features X2@W2
__device__ float g_as2[MAXN];
__device__ float g_ad2[MAXN];
__device__ int   g_deg[MAXN];       // zero at load; re-zeroed in scan each run
__device__ int   g_rowptr[MAXN + 1];
__device__ int   g_wpos[MAXN + 1];
__device__ int   g_csrsrc[MAXE];
__device__ float4 g_w1[MAXE];       // layer-1 edge weights (4 heads), CSR order
__device__ int   g_bsums[64];
__device__ float g_v2s[64];         // W2@a_src2
__device__ float g_v2d[64];         // W2@a_dst2
__device__ int   g_cnt1;            // scan barrier counters (self-resetting)
__device__ int   g_cnt2;

// ---------------- L1: fused GEMM1 (+alpha epilogue) ⊕ edge histogram --------
__global__ void k_gemm1_hist(const float* __restrict__ x, const float* __restrict__ W1,
                             const float* __restrict__ a_src, const float* __restrict__ a_dst,
                             const int* __restrict__ ei, int N, int E, int gemmBlocks) {
    __shared__ float Wsh[128 * 64];   // 32 KB
    __shared__ float xs[128][17];

    if (blockIdx.x >= gemmBlocks) {
        int nb = gridDim.x - gemmBlocks;
        int stride = nb * blockDim.x;
        for (int e = (blockIdx.x - gemmBlocks) * blockDim.x + threadIdx.x; e < E; e += stride)
            atomicAdd(&g_deg[ei[E + e]], 1);
        return;
    }

    int t = threadIdx.x;
    int n0 = blockIdx.x * 128;
    for (int i = t; i < 128 * 64; i += 256) Wsh[i] = W1[i];

    int ng = t >> 3;
    int cg = t & 7;
    float acc[4][8];
#pragma unroll
    for (int r = 0; r < 4; ++r)
#pragma unroll
        for (int j = 0; j < 8; ++j) acc[r][j] = 0.f;

    for (int kt = 0; kt < 128; kt += 16) {
        __syncthreads();
        for (int i = t; i < 128 * 16; i += 256) {
            int n = i >> 4, kk = i & 15;
            int gn = n0 + n;
            xs[n][kk] = (gn < N) ? x[gn * 128 + kt + kk] : 0.f;
        }
        __syncthreads();
#pragma unroll
        for (int kk = 0; kk < 16; ++kk) {
            float wv[8];
#pragma unroll
            for (int j = 0; j < 8; ++j) wv[j] = Wsh[(kt + kk) * 64 + cg * 8 + j];
#pragma unroll
            for (int r = 0; r < 4; ++r) {
                float xv = xs[ng * 4 + r][kk];
#pragma unroll
                for (int j = 0; j < 8; ++j) acc[r][j] = fmaf(xv, wv[j], acc[r][j]);
            }
        }
    }

    float asw[8], adw[8];
#pragma unroll
    for (int j = 0; j < 8; ++j) { asw[j] = __ldg(&a_src[cg * 8 + j]); adw[j] = __ldg(&a_dst[cg * 8 + j]); }

#pragma unroll
    for (int r = 0; r < 4; ++r) {
        int gn = n0 + ng * 4 + r;
        float ps = 0.f, pd = 0.f;
#pragma unroll
        for (int j = 0; j < 8; ++j) { ps = fmaf(acc[r][j], asw[j], ps); pd = fmaf(acc[r][j], adw[j], pd); }
        ps += __shfl_xor_sync(0xffffffffu, ps, 1);
        pd += __shfl_xor_sync(0xffffffffu, pd, 1);
        if (gn < N) {
            float4* dst = reinterpret_cast<float4*>(&g_H1[gn * 64 + cg * 8]);
            dst[0] = make_float4(acc[r][0], acc[r][1], acc[r][2], acc[r][3]);
            dst[1] = make_float4(acc[r][4], acc[r][5], acc[r][6], acc[r][7]);
            if ((cg & 1) == 0) {
                g_as1[gn * 4 + (cg >> 1)] = ps;
                g_ad1[gn * 4 + (cg >> 1)] = pd;
            }
        }
    }
}

// ---------------- L2: single-launch scan (device barrier) ⊕ vpre -------------
// blocks [0,nb): tile scan + cross-block offset via counter barrier (single
// wave: nb+1 <= 50 blocks, all co-resident on 148 SMs -> no deadlock).
// block nb: v2 = W2 @ a2 projections.
__global__ void k_scan_fused(const float* __restrict__ W2,
                             const float* __restrict__ a_src2, const float* __restrict__ a_dst2,
                             int N, int nb) {
    int t = threadIdx.x;
    int bid = blockIdx.x;
    if (bid == nb) {
        if (t < 64) {
            float s2 = 0.f, d2 = 0.f;
#pragma unroll
            for (int j = 0; j < 32; ++j) {
                float wv = W2[t * 32 + j];
                s2 = fmaf(wv, a_src2[j], s2);
                d2 = fmaf(wv, a_dst2[j], d2);
            }
            g_v2s[t] = s2;
            g_v2d[t] = d2;
        }
        return;
    }

    __shared__ int wsum[32];
    __shared__ int sh_off;
    int lane = t & 31, wid = t >> 5;
    int i = bid * 1024 + t;
    int v = (i < N) ? g_deg[i] : 0;
    if (i < N) g_deg[i] = 0;
    int xx = v;
#pragma unroll
    for (int o = 1; o < 32; o <<= 1) {
        int u = __shfl_up_sync(0xffffffffu, xx, o);
        if (lane >= o) xx += u;
    }
    if (lane == 31) wsum[wid] = xx;
    __syncthreads();
    if (wid == 0) {
        int w = wsum[lane];
#pragma unroll
        for (int o = 1; o < 32; o <<= 1) {
            int u = __shfl_up_sync(0xffffffffu, w, o);
            if (lane >= o) w += u;
        }
        wsum[lane] = w;
    }
    __syncthreads();
    int woff = (wid > 0) ? wsum[wid - 1] : 0;
    int incl = woff + xx;

    // publish tile total, then barrier across scan blocks
    if (t == 1023) {
        g_bsums[bid] = incl;
        __threadfence();
        atomicAdd(&g_cnt1, 1);
    }
    if (t == 0) {
        while (*(volatile int*)&g_cnt1 < nb) {}
    }
    __syncthreads();
    __threadfence();   // acquire: make all g_bsums visible

    // warp 0 computes this block's exclusive offset from bsums
    if (t < 32) {
        int l = t;
        int v1 = (l < nb) ? g_bsums[l] : 0;
        int v2 = (l + 32 < nb) ? g_bsums[l + 32] : 0;
#pragma unroll
        for (int o = 1; o < 32; o <<= 1) {
            int u = __shfl_up_sync(0xffffffffu, v1, o);
            if (l >= o) v1 += u;
        }
        int tot1 = __shfl_sync(0xffffffffu, v1, 31);
#pragma unroll
        for (int o = 1; o < 32; o <<= 1) {
            int u = __shfl_up_sync(0xffffffffu, v2, o);
            if (l >= o) v2 += u;
        }
        int ex;
        if (bid == 0) ex = 0;
        else if (bid - 1 < 32) ex = __shfl_sync(0xffffffffu, v1, bid - 1);
        else ex = tot1 + __shfl_sync(0xffffffffu, v2, bid - 1 - 32);
        if (l == 0) sh_off = ex;
    }
    __syncthreads();
    int off = sh_off;
    if (i < N) {
        int val = incl + off;
        g_rowptr[i + 1] = val;
        g_wpos[i + 1] = val;
    }
    if (bid == 0 && t == 0) { g_rowptr[0] = 0; g_wpos[0] = 0; }

    // reset counters for the next graph replay (last block to finish does it)
    __syncthreads();
    if (t == 0) {
        int done = atomicAdd(&g_cnt2, 1);
        if (done == nb - 1) { g_cnt1 = 0; g_cnt2 = 0; }
    }
}

// ---------------- L3: CSR fill + layer-1 edge weights ------------------------
__global__ void __launch_bounds__(256) k_fillw(const int* __restrict__ ei, int E) {
    int e = blockIdx.x * blockDim.x + threadIdx.x;
    if (e >= E) return;
    int src = ei[e];
    int dst = ei[E + e];
    int p = atomicAdd(&g_wpos[dst], 1);
    g_csrsrc[p] = src;
    float4 as = __ldg(reinterpret_cast<const float4*>(&g_as1[src * 4]));
    float4 ad = __ldg(reinterpret_cast<const float4*>(&g_ad1[dst * 4]));
    float4 w;
    float e0 = as.x + ad.x; w.x = __expf(fmaxf(e0, 0.2f * e0));
    float e1 = as.y + ad.y; w.y = __expf(fmaxf(e1, 0.2f * e1));
    float e2 = as.z + ad.z; w.z = __expf(fmaxf(e2, 0.2f * e2));
    float e3 = as.w + ad.w; w.w = __expf(fmaxf(e3, 0.2f * e3));
    g_w1[p] = w;
}

// ---------------- L4: layer-1 agg: QUARTER-WARP per node (8 lanes, 8 ch) -----
__global__ void k_agg1(const float* __restrict__ b1, int N) {
    int warp = (blockIdx.x * blockDim.x + threadIdx.x) >> 5;
    int lane = threadIdx.x & 31;
    int q = lane >> 3;          // node slot 0..3
    int hl = lane & 7;          // lane-in-group 0..7
    unsigned gmask = 0xffu << (q * 8);
    int node = warp * 4 + q;
    if (node >= N) return;
    int beg = g_rowptr[node], end = g_rowptr[node + 1];
    int ch = hl * 8;            // 8 channels per lane
    int head = hl >> 1;         // 16 channels per head
    const float* w1f = reinterpret_cast<const float*>(g_w1);

    float s = 0.f;
    float a[8] = {0, 0, 0, 0, 0, 0, 0, 0};
    for (int p = beg; p < end; ++p) {
        int src = g_csrsrc[p];
        float w = __ldg(&w1f[p * 4 + head]);
        const float4* hp = reinterpret_cast<const float4*>(&g_H1[src * 64 + ch]);
        float4 h0 = hp[0];
        float4 h1 = hp[1];
        s += w;
        a[0] = fmaf(w, h0.x, a[0]);
        a[1] = fmaf(w, h0.y, a[1]);
        a[2] = fmaf(w, h0.z, a[2]);
        a[3] = fmaf(w, h0.w, a[3]);
        a[4] = fmaf(w, h1.x, a[4]);
        a[5] = fmaf(w, h1.y, a[5]);
        a[6] = fmaf(w, h1.z, a[6]);
        a[7] = fmaf(w, h1.w, a[7]);
    }
    float inv = 1.f / (s + 1e-16f);
    float4 bb0 = *reinterpret_cast<const float4*>(&b1[ch]);
    float4 bb1 = *reinterpret_cast<const float4*>(&b1[ch + 4]);
    float o[8];
    o[0] = fmaf(a[0], inv, bb0.x); o[1] = fmaf(a[1], inv, bb0.y);
    o[2] = fmaf(a[2], inv, bb0.z); o[3] = fmaf(a[3], inv, bb0.w);
    o[4] = fmaf(a[4], inv, bb1.x); o[5] = fmaf(a[5], inv, bb1.y);
    o[6] = fmaf(a[6], inv, bb1.z); o[7] = fmaf(a[7], inv, bb1.w);
#pragma unroll
    for (int j = 0; j < 8; ++j) o[j] = (o[j] > 0.f) ? o[j] : expm1f(o[j]);   // elu
    float4* xo = reinterpret_cast<float4*>(&g_X2[node * 64 + ch]);
    xo[0] = make_float4(o[0], o[1], o[2], o[3]);
    xo[1] = make_float4(o[4], o[5], o[6], o[7]);

    // epilogue: as2/ad2 = X2row . v2 (8-lane group reduction)
    const float4* vsp = reinterpret_cast<const float4*>(&g_v2s[ch]);
    const float4* vdp = reinterpret_cast<const float4*>(&g_v2d[ch]);
    float4 vs0 = vsp[0], vs1 = vsp[1], vd0 = vdp[0], vd1 = vdp[1];
    float ps = o[0]*vs0.x + o[1]*vs0.y + o[2]*vs0.z + o[3]*vs0.w
             + o[4]*vs1.x + o[5]*vs1.y + o[6]*vs1.z + o[7]*vs1.w;
    float pd = o[0]*vd0.x + o[1]*vd0.y + o[2]*vd0.z + o[3]*vd0.w
             + o[4]*vd1.x + o[5]*vd1.y + o[6]*vd1.z + o[7]*vd1.w;
#pragma unroll
    for (int off = 1; off < 8; off <<= 1) {
        ps += __shfl_xor_sync(gmask, ps, off);
        pd += __shfl_xor_sync(gmask, pd, off);
    }
    if (hl == 0) { g_as2[node] = ps; g_ad2[node] = pd; }
}

// ---------------- L5: GEMM2 ---------------------------------------------------
__global__ void k_gemm2(const float* __restrict__ W2, int N) {
    __shared__ float Wsh[64 * 32];
    __shared__ float xs[128][65];
    int t = threadIdx.x;
    int n0 = blockIdx.x * 128;
    for (int i = t; i < 64 * 32; i += 128) Wsh[i] = W2[i];
    for (int i = t; i < 128 * 64; i += 128) {
        int n = i >> 6, k = i & 63;
        int gn = n0 + n;
        xs[n][k] = (gn < N) ? g_X2[gn * 64 + k] : 0.f;
    }
    __syncthreads();
    int ng = t >> 2;
    int cg = t & 3;
    float acc[4][8];
#pragma unroll
    for (int r = 0; r < 4; ++r)
#pragma unroll
        for (int j = 0; j < 8; ++j) acc[r][j] = 0.f;
#pragma unroll 4
    for (int k = 0; k < 64; ++k) {
        float wv[8];
#pragma unroll
        for (int j = 0; j < 8; ++j) wv[j] = Wsh[k * 32 + cg * 8 + j];
#pragma unroll
        for (int r = 0; r < 4; ++r) {
            float xv = xs[ng * 4 + r][k];
#pragma unroll
            for (int j = 0; j < 8; ++j) acc[r][j] = fmaf(xv, wv[j], acc[r][j]);
        }
    }
#pragma unroll
    for (int r = 0; r < 4; ++r) {
        int gn = n0 + ng * 4 + r;
        if (gn < N) {
            float4* dst = reinterpret_cast<float4*>(&g_H2[gn * 32 + cg * 8]);
            dst[0] = make_float4(acc[r][0], acc[r][1], acc[r][2], acc[r][3]);
            dst[1] = make_float4(acc[r][4], acc[r][5], acc[r][6], acc[r][7]);
        }
    }
}

// ---------------- L6: layer-2 agg: QUARTER-WARP per node (8 lanes, 4 ch) -----
__global__ void k_agg2(const float* __restrict__ b2, float* __restrict__ out, int N) {
    int warp = (blockIdx.x * blockDim.x + threadIdx.x) >> 5;
    int lane = threadIdx.x & 31;
    int q = lane >> 3;
    int hl = lane & 7;
    int node = warp * 4 + q;
    if (node >= N) return;
    int beg = g_rowptr[node], end = g_rowptr[node + 1];
    int ch = hl * 4;
    float adv = g_ad2[node];

    float s = 0.f;
    float a0 = 0.f, a1 = 0.f, a2 = 0.f, a3 = 0.f;
    for (int p = beg; p < end; ++p) {
        int src = g_csrsrc[p];
        float e = __ldg(&g_as2[src]) + adv;
        float4 h = *reinterpret_cast<const float4*>(&g_H2[src * 32 + ch]);
        float w = __expf(fmaxf(e, 0.2f * e));
        s += w;
        a0 = fmaf(w, h.x, a0);
        a1 = fmaf(w, h.y, a1);
        a2 = fmaf(w, h.z, a2);
        a3 = fmaf(w, h.w, a3);
    }
    float inv = 1.f / (s + 1e-16f);
    float4 bb = *reinterpret_cast<const float4*>(&b2[ch]);
    float4 o;
    o.x = fmaf(a0, inv, bb.x);
    o.y = fmaf(a1, inv, bb.y);
    o.z = fmaf(a2, inv, bb.z);
    o.w = fmaf(a3, inv, bb.w);
    *reinterpret_cast<float4*>(&out[node * 32 + ch]) = o;
}

// ---------------- launch -----------------------------------------------------
extern "C" void kernel_launch(void* const* d_in, const int* in_sizes, int n_in,
                              void* d_out, int out_size) {
    const float* x      = (const float*)d_in[0];
    const int*   ei     = (const int*)  d_in[1];
    const float* W1     = (const float*)d_in[2];
    const float* a_src1 = (const float*)d_in[3];
    const float* a_dst1 = (const float*)d_in[4];
    const float* b1     = (const float*)d_in[5];
    const float* W2     = (const float*)d_in[6];
    const float* a_src2 = (const float*)d_in[7];
    const float* a_dst2 = (const float*)d_in[8];
    const float* b2     = (const float*)d_in[9];

    int N = in_sizes[0] / 128;
    int E = in_sizes[1] / 2;
    int nb = (N + 1023) / 1024;

    int gemmBlocks = (N + 127) / 128;
    int histBlocks = 1184;
    int aggWarps = (N + 3) / 4;          // 4 nodes per warp

    // L1: GEMM1(+alphas1) overlapped with edge histogram
    k_gemm1_hist<<<gemmBlocks + histBlocks, 256>>>(x, W1, a_src1, a_dst1, ei, N, E, gemmBlocks);
    // L2: single-launch scan (device barrier) + v2 projections
    k_scan_fused<<<nb + 1, 1024>>>(W2, a_src2, a_dst2, N, nb);
    // L3: CSR fill + layer-1 edge weights
    k_fillw<<<(E + 255) / 256, 256>>>(ei, E);
    // L4: layer-1 aggregation (+elu, +as2/ad2)
    k_agg1<<<(aggWarps * 32 + 255) / 256, 256>>>(b1, N);
    // L5: GEMM2
    k_gemm2<<<(N + 127) / 128, 128>>>(W2, N);
    // L6: layer-2 aggregation (inline w2)
    k_agg2<<<(aggWarps * 32 + 255) / 256, 256>>>(b2, (float*)d_out, N);
}